// round 17
// baseline (speedup 1.0000x reference)
#include <cuda_runtime.h>
#include <stdint.h>
#include <math.h>

#define BS   8
#define CCH  256
#define NND  9216     // H*W
#define EED  9215     // N-1 edges
#define ZETA 0.01f

#define CPB  16               // channels per dist block
#define GQ   (CCH/CPB)        // 16 groups per batch
#define TCH  2                // channels per tile step
#define NSTEP (CPB/TCH)       // 8 tile steps
#define TILEB (TCH*NND*4)     // 73728 bytes per tile
#define NT   1024
#define EPT  9                // ceil(EED/NT)
#define NCHUNK (NND/NT)       // 9
#define GRID (BS*GQ + 2*BS)   // 128 dist + 16 pass = 144 (<=148, co-resident)

// static device scratch (zero-init at load; counters/flags self-resetting)
__device__ float g_sum[(size_t)BS * EED];        // per-edge squared dist
__device__ float g_Z[(size_t)BS * NND];          // G field (denominator)
__device__ int   g_done[BS];                     // dist blocks finished
__device__ int   g_flagW[BS];                    // F-block done reading g_sum
__device__ int   g_flagZ[BS];                    // Z published

extern __shared__ float dyn_smem[];

__device__ __forceinline__ uint32_t smem_u32(const void* p) {
    return (uint32_t)__cvta_generic_to_shared(p);
}
__device__ __forceinline__ void mbar_init(uint32_t mbar, uint32_t cnt) {
    asm volatile("mbarrier.init.shared.b64 [%0], %1;" :: "r"(mbar), "r"(cnt)
                 : "memory");
}
__device__ __forceinline__ void mbar_expect_tx(uint32_t mbar, uint32_t tx) {
    asm volatile("mbarrier.arrive.expect_tx.shared.b64 _, [%0], %1;"
                 :: "r"(mbar), "r"(tx) : "memory");
}
__device__ __forceinline__ void bulk_g2s(uint32_t dst, const void* src,
                                         uint32_t bytes, uint32_t mbar) {
    asm volatile(
        "cp.async.bulk.shared::cta.global.mbarrier::complete_tx::bytes "
        "[%0], [%1], %2, [%3];"
        :: "r"(dst), "l"(src), "r"(bytes), "r"(mbar) : "memory");
}
__device__ __forceinline__ void mbar_wait(uint32_t mbar, uint32_t phase) {
    uint32_t done;
    asm volatile(
        "{\n\t.reg .pred p;\n\t"
        "mbarrier.try_wait.parity.acquire.cta.shared::cta.b64 p, [%1], %2;\n\t"
        "selp.b32 %0, 1, 0, p;\n\t}"
        : "=r"(done) : "r"(mbar), "r"(phase) : "memory");
    while (!done) {
        asm volatile(
            "{\n\t.reg .pred p;\n\t"
            "mbarrier.try_wait.parity.acquire.cta.shared::cta.b64 p, [%1], %2, 0x989680;\n\t"
            "selp.b32 %0, 1, 0, p;\n\t}"
            : "=r"(done) : "r"(mbar), "r"(phase) : "memory");
    }
}
__device__ __forceinline__ void fence_proxy_async_cta() {
    asm volatile("fence.proxy.async.shared::cta;" ::: "memory");
}

// ---------------------------------------------------------------------------
// Dist role: blocks 0..127 (unchanged from R16 — bulk-TMA double buffering).
// ---------------------------------------------------------------------------
__device__ void dist_role(const float* __restrict__ emb,
                          const int*   __restrict__ tree, int id) {
    __shared__ __align__(8) uint64_t mbar_s[2];
    float* buf[2] = { dyn_smem, dyn_smem + TCH * NND };
    const int b   = id / GQ;
    const int g   = id % GQ;
    const int tid = threadIdx.x;

    const float* base = emb + ((size_t)b * CCH + (size_t)g * CPB) * NND;
    uint32_t mb[2] = { smem_u32(&mbar_s[0]), smem_u32(&mbar_s[1]) };
    uint32_t bufa[2] = { smem_u32(buf[0]), smem_u32(buf[1]) };

    if (tid == 0) {
        mbar_init(mb[0], 1);
        mbar_init(mb[1], 1);
        fence_proxy_async_cta();
    }
    __syncthreads();

    if (tid == 0) {
        mbar_expect_tx(mb[0], TILEB);
        bulk_g2s(bufa[0], base, TILEB, mb[0]);
    }

    const int2* tr2 = (const int2*)(tree + (size_t)b * EED * 2);
    int2 ed[EPT];
    float acc[EPT];
#pragma unroll
    for (int k = 0; k < EPT; k++) {
        int e = tid + k * NT;
        ed[k]  = (e < EED) ? tr2[e] : make_int2(0, 0);
        acc[k] = 0.f;
    }

    int ph0 = 0, ph1 = 0;
    for (int t = 0; t < NSTEP; t++) {
        if (t + 1 < NSTEP && tid == 0) {
            int nb = (t + 1) & 1;
            mbar_expect_tx(mb[nb], TILEB);
            bulk_g2s(bufa[nb], base + (size_t)(t + 1) * TCH * NND,
                     TILEB, mb[nb]);
        }
        if ((t & 1) == 0) { mbar_wait(mb[0], ph0); ph0 ^= 1; }
        else              { mbar_wait(mb[1], ph1); ph1 ^= 1; }

        const float* cur = buf[t & 1];
#pragma unroll
        for (int k = 0; k < EPT; k++) {
            float a0 = cur[ed[k].x];
            float b0 = cur[ed[k].y];
            float a1 = cur[NND + ed[k].x];
            float b1 = cur[NND + ed[k].y];
            float d0 = a0 - b0, d1 = a1 - b1;
            acc[k] += d0 * d0 + d1 * d1;
        }
        __syncthreads();
    }

    float* sp = g_sum + (size_t)b * EED;
#pragma unroll
    for (int k = 0; k < EPT; k++) {
        int e = tid + k * NT;
        if (e < EED) atomicAdd(sp + e, acc[k]);
    }

    __threadfence();
    __syncthreads();
    if (tid == 0) atomicAdd(&g_done[b], 1);
}

// ---------------------------------------------------------------------------
// Pass role: blocks 128..143 = (batch, field). Root-path-normalized passes:
//   A[i]   = prod of edge weights root->i            (chunked product walk)
//   T[i]   = sum_{j in subtree(i)} A[j]*f_j          (reverse-chunk push)
//   S_up   = T/A ;  F = down-pass affine chunk walk  (as R15)
// No level sort, no histogram. All walks exploit parent < child.
// smem: par i[N] | wnode f[N] | S f[N] | AF f[N] | acc f[N] | wacc f[N]
// ---------------------------------------------------------------------------
__device__ void pass_role(const float* __restrict__ fin,
                          const int*   __restrict__ tree,
                          float*       __restrict__ out,
                          int b, int which) {
    const int tid = threadIdx.x;

    int*   par   = (int*)dyn_smem;
    float* wnode = dyn_smem + NND;
    float* S     = dyn_smem + 2 * NND;
    float* AF    = dyn_smem + 3 * NND;   // A in up phase, F in down phase
    float* acc   = dyn_smem + 4 * NND;
    float* wacc  = dyn_smem + 5 * NND;

    const int2* tr2 = (const int2*)(tree + (size_t)b * EED * 2);

    // ===== init (tree-only; overlapped with dist) ==========================
    if (tid == 0) { par[0] = 0; AF[0] = 1.f; wnode[0] = 1.f; }
    for (int i = 1 + tid; i < NND; i += NT) par[i] = tr2[i - 1].x;
    for (int i = tid; i < NND; i += NT) { acc[i] = 0.f; wacc[i] = 0.f; }
    if (which == 0) {
        const float* fb = fin + (size_t)b * NND;
        for (int i = tid; i < NND; i += NT) S[i] = fb[i];
    } else {
        for (int i = tid; i < NND; i += NT) S[i] = 1.f;
    }
    __syncthreads();

    // ===== wait for dist ====================================================
    if (tid == 0) {
        while (atomicAdd(&g_done[b], 0) < GQ) __nanosleep(64);
        __threadfence();
    }
    __syncthreads();

    // ===== node weights (child of edge e is e+1 -> coalesced) ==============
    const float* sp = g_sum + (size_t)b * EED;
    for (int i = 1 + tid; i < NND; i += NT)
        wnode[i] = __expf(-ZETA * __ldcg(sp + (i - 1)));
    __syncthreads();
    if (which == 0 && tid == 0) {
        __threadfence();
        atomicExch(&g_flagW[b], 1);      // done reading g_sum
    }

    // ===== A: root-path weight products (chunked walk) =====================
#pragma unroll 1
    for (int c = 0; c < NCHUNK; c++) {
        int i = c * NT + tid;
        if (i > 0) {
            int base = (c == 0) ? 1 : c * NT;
            float a = wnode[i];
            int j = par[i];
            while (j >= base) { a *= wnode[j]; j = par[j]; }
            AF[i] = a * AF[j];
        }
        __syncthreads();
    }

    // ===== UP: T[i] = sum_subtree A*f via reverse-chunk push ===============
#pragma unroll 1
    for (int c = NCHUNK - 1; c >= 0; --c) {
        int i = c * NT + tid;
        int cstart = c * NT;
        float X = AF[i] * S[i] + acc[i];
        if (i > 0) {
            int j = par[i];
            while (j >= cstart) {
                atomicAdd(&wacc[j], X);
                if (j == 0) break;
                j = par[j];
            }
        }
        __syncthreads();
        float T = X + wacc[i];
        S[i] = T / AF[i];                // S_up
        if (i > 0) {
            int p = par[i];
            if (p < cstart) atomicAdd(&acc[p], T);
        }
        __syncthreads();
    }

    // ===== DOWN: affine chunk walk (F overwrites AF) ========================
    if (tid == 0) AF[0] = S[0];
    __syncthreads();
#pragma unroll 1
    for (int c = 0; c < NCHUNK; c++) {
        int i = c * NT + tid;
        if (i > 0) {
            int base = (c == 0) ? 1 : c * NT;
            float wi = wnode[i];
            float a  = wi;
            float bb = (1.f - wi * wi) * S[i];
            int j = par[i];
            while (j >= base) {
                float wj = wnode[j];
                bb += a * ((1.f - wj * wj) * S[j]);
                a  *= wj;
                j = par[j];
            }
            AF[i] = a * AF[j] + bb;
        }
        __syncthreads();
    }

    // ===== exchange + output + replay hygiene ===============================
    if (which == 1) {
        float* zp = g_Z + (size_t)b * NND;
        for (int i = tid; i < NND; i += NT) zp[i] = AF[i];
        __threadfence();
        __syncthreads();
        if (tid == 0) {
            atomicExch(&g_flagZ[b], 1);
            while (atomicAdd(&g_flagW[b], 0) == 0) __nanosleep(64);
            atomicExch(&g_flagW[b], 0);        // reset for next replay
        }
        __syncthreads();
        float* spw = g_sum + (size_t)b * EED;
        for (int e = tid; e < EED; e += NT) spw[e] = 0.f;
        if (tid == 0) atomicExch(&g_done[b], 0);   // reset for next replay
    } else {
        if (tid == 0) {
            while (atomicAdd(&g_flagZ[b], 0) == 0) __nanosleep(64);
            __threadfence();
            atomicExch(&g_flagZ[b], 0);        // reset for next replay
        }
        __syncthreads();
        const float* zp = g_Z + (size_t)b * NND;
        float* ob = out + (size_t)b * NND;
        for (int i = tid; i < NND; i += NT) ob[i] = AF[i] / __ldcg(zp + i);
    }
}

// ---------------------------------------------------------------------------
__global__ void __launch_bounds__(NT, 1)
mega_kernel(const float* __restrict__ fin,
            const float* __restrict__ emb,
            const int*   __restrict__ tree,
            float*       __restrict__ out) {
    if (blockIdx.x < BS * GQ) {
        dist_role(emb, tree, blockIdx.x);
    } else {
        int r = blockIdx.x - BS * GQ;
        pass_role(fin, tree, out, r >> 1, r & 1);
    }
}

// ---------------------------------------------------------------------------
extern "C" void kernel_launch(void* const* d_in, const int* in_sizes, int n_in,
                              void* d_out, int out_size) {
    const float* f    = (const float*)d_in[0];   // feature_in [8,1,96,96]
    const float* emb  = (const float*)d_in[1];   // embed_in   [8,256,96,96]
    const int*   tree = (const int*)d_in[2];     // tree       [8,9215,2]
    float*       out  = (float*)d_out;           // [8,1,96,96]

    size_t smem = 6 * (size_t)NND * sizeof(float);   // 221184 B
    cudaFuncSetAttribute(mega_kernel,
                         cudaFuncAttributeMaxDynamicSharedMemorySize,
                         (int)smem);
    mega_kernel<<<GRID, NT, smem>>>(f, emb, tree, out);
}